// round 14
// baseline (speedup 1.0000x reference)
#include <cuda_runtime.h>
#include <math.h>

// ---------------- problem constants ----------------
#define NB   50                  // graphs
#define NPG  2000                // nodes per graph (layer 0)
#define EPG  12000               // edges per graph
#define ET   (NB*EPG)            // 600000 total edge slots (fixed across layers)
#define N0   (NB*NPG)            // 100000 nodes (layer 0)
#define FIN  256
#define NH   128

// ---------------- scratch (device globals; no allocations) ----------------
static __device__ float g_bufA[(size_t)N0*NH];   // conv output (relu'd)
static __device__ float g_bufB[(size_t)N0*NH];   // pooled features / conv input
static __device__ float g_H   [(size_t)N0*NH];   // X @ W
static __device__ float g_sh  [N0];              // score-conv pre-agg (X @ Ws)
static __device__ float g_score[N0];
static __device__ float g_dis [N0];              // rsqrt(deg)
static __device__ int   g_cnt [N0];              // valid in-edge count
static __device__ int   g_map [N0];              // old -> new node id (-1 dropped)
static __device__ int   g_rowptr[N0+1];
static __device__ int   g_cur [N0];
static __device__ int   g_col [ET];
static __device__ int   g_esrc[ET];              // -1 marks invalid edge
static __device__ int   g_edst[ET];
static __device__ int   g_perm[80000];
static __device__ float g_gmul[80000];
static __device__ int   g_bsum[64];
static __device__ float g_R[3*NB*2*NH];          // readouts per layer

// ---------------- small utility kernels ----------------
__global__ void k_init_edges(const int* __restrict__ ei) {
    int i = blockIdx.x*blockDim.x + threadIdx.x;
    if (i < ET) { g_esrc[i] = ei[i]; g_edst[i] = ei[ET + i]; }
}

__global__ void k_zero_cnt(int NL) {
    int i = blockIdx.x*blockDim.x + threadIdx.x;
    if (i < NL) g_cnt[i] = 0;
}

__global__ void k_count() {
    int e = blockIdx.x*blockDim.x + threadIdx.x;
    if (e >= ET) return;
    int s = g_esrc[e];
    if (s >= 0) atomicAdd(&g_cnt[g_edst[e]], 1);
}

// exclusive scan over length len = NL+1 (virtual value at NL is 0)
__global__ void k_scanA(int len, int NL) {
    __shared__ int sA[2048], sB[2048];
    int t = threadIdx.x;
    int base = blockIdx.x*2048;
    int i0 = base + t, i1 = base + t + 1024;
    int v0 = (i0 < NL) ? g_cnt[i0] : 0;
    int v1 = (i1 < NL) ? g_cnt[i1] : 0;
    sA[t] = v0; sA[t+1024] = v1;
    int* src = sA; int* dst = sB;
    #pragma unroll
    for (int off = 1; off < 2048; off <<= 1) {
        __syncthreads();
        int a0 = src[t]      + ((t      >= off) ? src[t-off]      : 0);
        int a1 = src[t+1024] + ((t+1024 >= off) ? src[t+1024-off] : 0);
        dst[t] = a0; dst[t+1024] = a1;
        int* tmp = src; src = dst; dst = tmp;
    }
    __syncthreads();
    if (i0 < len) g_rowptr[i0] = src[t]      - v0;
    if (i1 < len) g_rowptr[i1] = src[t+1024] - v1;
    if (t == 0) g_bsum[blockIdx.x] = src[2047];
}

__global__ void k_scanB(int nb) {
    if (threadIdx.x == 0) {
        int run = 0;
        for (int i = 0; i < nb; i++) { int v = g_bsum[i]; g_bsum[i] = run; run += v; }
    }
}

__global__ void k_scanC(int len) {
    int base = blockIdx.x*2048;
    int add = g_bsum[blockIdx.x];
    int i0 = base + threadIdx.x, i1 = i0 + 1024;
    if (i0 < len) g_rowptr[i0] += add;
    if (i1 < len) g_rowptr[i1] += add;
}

__global__ void k_copy_cur(int NL) {
    int i = blockIdx.x*blockDim.x + threadIdx.x;
    if (i < NL) g_cur[i] = g_rowptr[i];
}

__global__ void k_fill() {
    int e = blockIdx.x*blockDim.x + threadIdx.x;
    if (e >= ET) return;
    int s = g_esrc[e];
    if (s < 0) return;
    int d = g_edst[e];
    int p = atomicAdd(&g_cur[d], 1);
    g_col[p] = s;
}

// per-row insertion sort -> bitwise-deterministic summation order
__global__ void k_sortrows(int NL) {
    int node = blockIdx.x*blockDim.x + threadIdx.x;
    if (node >= NL) return;
    int beg = g_rowptr[node], end = g_rowptr[node+1];
    for (int i = beg + 1; i < end; i++) {
        int v = g_col[i]; int j = i - 1;
        while (j >= beg && g_col[j] > v) { g_col[j+1] = g_col[j]; j--; }
        g_col[j+1] = v;
    }
}

__global__ void k_dis(int NL) {
    int i = blockIdx.x*blockDim.x + threadIdx.x;
    if (i < NL) g_dis[i] = rsqrtf((float)(g_cnt[i] + 1));
}

// ---------------- SGEMM: g_H[M x 128] = A[M x K] * W[K x 128] ----------------
template<int K>
__global__ __launch_bounds__(256) void k_sgemm(const float* __restrict__ Aext,
                                               const float* __restrict__ W, int M) {
    const float* __restrict__ A = Aext ? Aext : g_bufB;
    __shared__ float As[16][128];   // transposed A tile
    __shared__ float Bs[16][128];
    int tid = threadIdx.x;
    int ty = tid >> 4, tx = tid & 15;
    int rowBase = blockIdx.x * 128;
    float acc[8][8];
    #pragma unroll
    for (int i = 0; i < 8; i++)
        #pragma unroll
        for (int j = 0; j < 8; j++) acc[i][j] = 0.f;

    for (int k0 = 0; k0 < K; k0 += 16) {
        #pragma unroll
        for (int l = 0; l < 2; l++) {
            int f = tid + l*256;
            int r = f >> 2, c = (f & 3) << 2;
            int gr = rowBase + r;
            float4 v = make_float4(0.f,0.f,0.f,0.f);
            if (gr < M) v = *(const float4*)(A + (size_t)gr*K + k0 + c);
            As[c+0][r] = v.x; As[c+1][r] = v.y; As[c+2][r] = v.z; As[c+3][r] = v.w;
        }
        #pragma unroll
        for (int l = 0; l < 2; l++) {
            int f = tid + l*256;
            int r = f >> 5, c = (f & 31) << 2;
            *(float4*)&Bs[r][c] = *(const float4*)(W + (size_t)(k0+r)*128 + c);
        }
        __syncthreads();
        #pragma unroll
        for (int kk = 0; kk < 16; kk++) {
            float a[8], bb[8];
            *(float4*)&a[0]  = *(float4*)&As[kk][ty*8];
            *(float4*)&a[4]  = *(float4*)&As[kk][ty*8+4];
            *(float4*)&bb[0] = *(float4*)&Bs[kk][tx*8];
            *(float4*)&bb[4] = *(float4*)&Bs[kk][tx*8+4];
            #pragma unroll
            for (int i = 0; i < 8; i++)
                #pragma unroll
                for (int j = 0; j < 8; j++)
                    acc[i][j] = fmaf(a[i], bb[j], acc[i][j]);
        }
        __syncthreads();
    }
    #pragma unroll
    for (int i = 0; i < 8; i++) {
        int gr = rowBase + ty*8 + i;
        if (gr < M) {
            *(float4*)(g_H + (size_t)gr*128 + tx*8)     = make_float4(acc[i][0],acc[i][1],acc[i][2],acc[i][3]);
            *(float4*)(g_H + (size_t)gr*128 + tx*8 + 4) = make_float4(acc[i][4],acc[i][5],acc[i][6],acc[i][7]);
        }
    }
}

// ---------------- GCN aggregation (warp per node, float4 per lane) ----------------
__global__ void k_agg_main(const float* __restrict__ bias, int NL) {
    int node = (blockIdx.x*blockDim.x + threadIdx.x) >> 5;
    int lane = threadIdx.x & 31;
    if (node >= NL) return;
    const float4* H4 = (const float4*)g_H;
    float4 acc = make_float4(0.f,0.f,0.f,0.f);
    int beg = g_rowptr[node], end = g_rowptr[node+1];
    for (int eb = beg; eb < end; eb += 32) {
        int m = min(32, end - eb);
        int   sl = (lane < m) ? g_col[eb + lane] : 0;
        float dl = (lane < m) ? g_dis[sl] : 0.f;
        for (int q = 0; q < m; q++) {
            int   s  = __shfl_sync(0xffffffffu, sl, q);
            float ds = __shfl_sync(0xffffffffu, dl, q);
            float4 h = H4[(size_t)s*32 + lane];
            acc.x = fmaf(h.x, ds, acc.x);
            acc.y = fmaf(h.y, ds, acc.y);
            acc.z = fmaf(h.z, ds, acc.z);
            acc.w = fmaf(h.w, ds, acc.w);
        }
    }
    float dd  = g_dis[node];
    float inv = 1.0f / (float)(g_cnt[node] + 1);
    float4 hs = H4[(size_t)node*32 + lane];
    float4 b4 = ((const float4*)bias)[lane];
    float4 o;
    o.x = fmaxf(acc.x*dd + hs.x*inv + b4.x, 0.f);
    o.y = fmaxf(acc.y*dd + hs.y*inv + b4.y, 0.f);
    o.z = fmaxf(acc.z*dd + hs.z*inv + b4.z, 0.f);
    o.w = fmaxf(acc.w*dd + hs.w*inv + b4.w, 0.f);
    ((float4*)g_bufA)[(size_t)node*32 + lane] = o;
}

// sh = bufA @ Ws  (warp per node)
__global__ void k_gemv(const float* __restrict__ Ws, int NL) {
    int node = (blockIdx.x*blockDim.x + threadIdx.x) >> 5;
    int lane = threadIdx.x & 31;
    if (node >= NL) return;
    float4 a = ((const float4*)g_bufA)[(size_t)node*32 + lane];
    float4 w = ((const float4*)Ws)[lane];
    float acc = a.x*w.x + a.y*w.y + a.z*w.z + a.w*w.w;
    #pragma unroll
    for (int o = 16; o; o >>= 1) acc += __shfl_xor_sync(0xffffffffu, acc, o);
    if (lane == 0) g_sh[node] = acc;
}

__global__ void k_agg_score(const float* __restrict__ bs, int NL) {
    int node = blockIdx.x*blockDim.x + threadIdx.x;
    if (node >= NL) return;
    float acc = 0.f;
    int beg = g_rowptr[node], end = g_rowptr[node+1];
    for (int e = beg; e < end; e++) {
        int s = g_col[e];
        acc = fmaf(g_sh[s], g_dis[s], acc);
    }
    float inv = 1.0f / (float)(g_cnt[node] + 1);
    g_score[node] = acc*g_dis[node] + g_sh[node]*inv + bs[0];
}

__global__ void k_fillmap(int NL) {
    int i = blockIdx.x*blockDim.x + threadIdx.x;
    if (i < NL) g_map[i] = -1;
}

// top-k per graph via bitonic sort of 2048 packed keys (score desc, idx asc)
__global__ void k_topk(int n, int k) {
    __shared__ unsigned long long key[2048];
    int b = blockIdx.x;
    for (int j = threadIdx.x; j < 2048; j += 1024) {
        unsigned long long kk;
        if (j < n) {
            unsigned int u = __float_as_uint(g_score[b*n + j]);
            u = (u & 0x80000000u) ? ~u : (u | 0x80000000u);  // monotone float->uint
            kk = ((unsigned long long)(~u) << 32) | (unsigned int)j;  // asc sort = score desc
        } else kk = 0xFFFFFFFFFFFFFFFFull;
        key[j] = kk;
    }
    for (int sz = 2; sz <= 2048; sz <<= 1)
        for (int st = sz >> 1; st > 0; st >>= 1) {
            __syncthreads();
            #pragma unroll 1
            for (int t = threadIdx.x; t < 2048; t += 1024) {
                int ixj = t ^ st;
                if (ixj > t) {
                    unsigned long long a = key[t], c = key[ixj];
                    bool up = ((t & sz) == 0);
                    if ((a > c) == up) { key[t] = c; key[ixj] = a; }
                }
            }
        }
    __syncthreads();
    for (int j = threadIdx.x; j < k; j += 1024) {
        int idx  = (int)(unsigned int)(key[j] & 0xffffffffull);
        int oldg = b*n + idx;
        int newg = b*k + j;
        g_perm[newg] = oldg;
        g_gmul[newg] = tanhf(g_score[oldg]);
        g_map[oldg]  = newg;
    }
}

__global__ void k_gather(int newN) {
    int i = blockIdx.x*blockDim.x + threadIdx.x;
    int node = i >> 5, lane = i & 31;
    if (node >= newN) return;
    int s = g_perm[node];
    float g = g_gmul[node];
    float4 v = ((const float4*)g_bufA)[(size_t)s*32 + lane];
    v.x *= g; v.y *= g; v.z *= g; v.w *= g;
    ((float4*)g_bufB)[(size_t)node*32 + lane] = v;
}

__global__ void k_remap() {
    int e = blockIdx.x*blockDim.x + threadIdx.x;
    if (e >= ET) return;
    int s = g_esrc[e];
    if (s < 0) return;
    int ns = g_map[s], nd = g_map[g_edst[e]];
    if (ns >= 0 && nd >= 0) { g_esrc[e] = ns; g_edst[e] = nd; }
    else g_esrc[e] = -1;
}

// readout: max || mean over each graph's k nodes (x is pooled = g_bufB)
__global__ void k_readout(int kcnt, int layer) {
    int b = blockIdx.x;
    int g = threadIdx.x >> 7;      // 8 groups
    int f = threadIdx.x & 127;
    float m = -INFINITY, s = 0.f;
    for (int j = g; j < kcnt; j += 8) {
        float v = g_bufB[(size_t)(b*kcnt + j)*NH + f];
        m = fmaxf(m, v); s += v;
    }
    __shared__ float sm[8][128], ss[8][128];
    sm[g][f] = m; ss[g][f] = s;
    __syncthreads();
    if (g == 0) {
        #pragma unroll
        for (int q = 1; q < 8; q++) { m = fmaxf(m, sm[q][f]); s += ss[q][f]; }
        float* R = g_R + (size_t)layer*NB*256 + (size_t)b*256;
        R[f]       = m;
        R[128 + f] = s / (float)kcnt;
    }
}

__global__ void k_final(const float* __restrict__ Wl, const float* __restrict__ bl,
                        float* __restrict__ out) {
    int b = blockIdx.x;
    int f = threadIdx.x;   // 128
    __shared__ float s[256];
    for (int c = f; c < 256; c += 128)
        s[c] = g_R[b*256 + c] + g_R[NB*256 + b*256 + c] + g_R[2*NB*256 + b*256 + c];
    __syncthreads();
    float acc = bl[f];
    #pragma unroll 8
    for (int c = 0; c < 256; c++) acc = fmaf(s[c], Wl[c*128 + f], acc);
    out[b*128 + f] = fmaxf(acc, 0.f);
}

// ---------------- driver ----------------
extern "C" void kernel_launch(void* const* d_in, const int* in_sizes, int n_in,
                              void* d_out, int out_size) {
    const float* x   = (const float*)d_in[0];
    const float* W_[3]  = { (const float*)d_in[1], (const float*)d_in[5], (const float*)d_in[9]  };
    const float* b_[3]  = { (const float*)d_in[2], (const float*)d_in[6], (const float*)d_in[10] };
    const float* Ws_[3] = { (const float*)d_in[3], (const float*)d_in[7], (const float*)d_in[11] };
    const float* bs_[3] = { (const float*)d_in[4], (const float*)d_in[8], (const float*)d_in[12] };
    const float* Wl = (const float*)d_in[13];
    const float* bl = (const float*)d_in[14];
    const int*   ei = (const int*)d_in[15];
    float* out = (float*)d_out;

    const int EB = (ET + 255) / 256;
    k_init_edges<<<EB, 256>>>(ei);

    int n  = NPG;
    int NL = N0;
    for (int L = 0; L < 3; L++) {
        int kk  = (n * 4) / 5;              // ceil(0.8*n) exact for 2000/1600/1280
        int len = NL + 1;
        int nb  = (len + 2047) / 2048;
        int NLB = (NL + 255) / 256;

        // ---- CSR build (dst-major), deterministic ----
        k_zero_cnt<<<NLB, 256>>>(NL);
        k_count   <<<EB, 256>>>();
        k_scanA   <<<nb, 1024>>>(len, NL);
        k_scanB   <<<1, 32>>>(nb);
        k_scanC   <<<nb, 1024>>>(len);
        k_copy_cur<<<NLB, 256>>>(NL);
        k_fill    <<<EB, 256>>>();
        k_sortrows<<<NLB, 256>>>(NL);
        k_dis     <<<NLB, 256>>>(NL);

        // ---- GCN conv (H = Xin @ W; agg + self + bias + relu -> bufA) ----
        if (L == 0) k_sgemm<FIN><<<(NL + 127) / 128, 256>>>(x,       W_[L], NL);
        else        k_sgemm<NH> <<<(NL + 127) / 128, 256>>>(nullptr, W_[L], NL);
        k_agg_main<<<(NL + 7) / 8, 256>>>(b_[L], NL);

        // ---- score conv (same graph) ----
        k_gemv     <<<(NL + 7) / 8, 256>>>(Ws_[L], NL);
        k_agg_score<<<NLB, 256>>>(bs_[L], NL);

        // ---- SAG pool ----
        k_fillmap<<<NLB, 256>>>(NL);
        k_topk   <<<NB, 1024>>>(n, kk);
        int newN = NB * kk;
        k_gather <<<(newN*32 + 255) / 256, 256>>>(newN);
        k_remap  <<<EB, 256>>>();

        // ---- readout on pooled x ----
        k_readout<<<NB, 1024>>>(kk, L);

        n = kk; NL = newN;
    }
    k_final<<<NB, 128>>>(Wl, bl, out);
    (void)in_sizes; (void)n_in; (void)out_size;
}

// round 16
// speedup vs baseline: 1.0653x; 1.0653x over previous
#include <cuda_runtime.h>
#include <math.h>

// ---------------- problem constants ----------------
#define NB   50                  // graphs
#define NPG  2000                // nodes per graph (layer 0)
#define EPG  12000               // edges per graph
#define ET   (NB*EPG)            // 600000 total edge slots (fixed across layers)
#define N0   (NB*NPG)            // 100000 nodes (layer 0)
#define FIN  256
#define NH   128

// ---------------- scratch (device globals; no allocations) ----------------
static __device__ __align__(16) float g_bufA[(size_t)N0*NH];   // conv output (relu'd)
static __device__ __align__(16) float g_bufB[(size_t)N0*NH];   // pooled features / conv input
static __device__ __align__(16) float g_H   [(size_t)N0*NH];   // X @ W
static __device__ float g_sh  [N0];              // score-conv pre-agg
static __device__ float g_dis [N0];              // rsqrt(deg)
static __device__ int   g_cnt [N0];              // valid in-edge count
static __device__ int   g_map [N0];              // old -> new node id (-1 dropped)
static __device__ int   g_rowptr[N0+1];
static __device__ int   g_cur [N0];
static __device__ int   g_col [ET];
static __device__ int   g_esrc[ET];              // -1 marks invalid edge
static __device__ int   g_edst[ET];
static __device__ int   g_perm[80000];
static __device__ float g_gmul[80000];
static __device__ int   g_bsum[64];
static __device__ float g_R[3*NB*2*NH];          // readouts per layer

// ---------------- packed f32x2 helpers (Blackwell FFMA2, PTX-only) ----------------
__device__ __forceinline__ unsigned long long pk2(float x, float y) {
    unsigned long long r;
    asm("mov.b64 %0, {%1,%2};" : "=l"(r) : "f"(x), "f"(y));
    return r;
}
__device__ __forceinline__ void upk2(unsigned long long v, float& x, float& y) {
    asm("mov.b64 {%0,%1}, %2;" : "=f"(x), "=f"(y) : "l"(v));
}
__device__ __forceinline__ void fma2(unsigned long long& d, unsigned long long a, unsigned long long b) {
    asm("fma.rn.f32x2 %0, %1, %2, %0;" : "+l"(d) : "l"(a), "l"(b));
}

// ---------------- small utility kernels ----------------
__global__ void k_zero_cnt(int NL) {
    int i = blockIdx.x*blockDim.x + threadIdx.x;
    if (i < NL) g_cnt[i] = 0;
}

// copy edges + count in-degrees (layer 0)
__global__ void k_init_edges(const int* __restrict__ ei) {
    int i = blockIdx.x*blockDim.x + threadIdx.x;
    if (i >= ET) return;
    int s = ei[i], d = ei[ET + i];
    g_esrc[i] = s; g_edst[i] = d;
    atomicAdd(&g_cnt[d], 1);
}

// exclusive scan over length len = NL+1 (virtual value at NL is 0)
__global__ void k_scanA(int len, int NL) {
    __shared__ int sA[2048], sB[2048];
    int t = threadIdx.x;
    int base = blockIdx.x*2048;
    int i0 = base + t, i1 = base + t + 1024;
    int v0 = (i0 < NL) ? g_cnt[i0] : 0;
    int v1 = (i1 < NL) ? g_cnt[i1] : 0;
    sA[t] = v0; sA[t+1024] = v1;
    int* src = sA; int* dst = sB;
    #pragma unroll
    for (int off = 1; off < 2048; off <<= 1) {
        __syncthreads();
        int a0 = src[t]      + ((t      >= off) ? src[t-off]      : 0);
        int a1 = src[t+1024] + ((t+1024 >= off) ? src[t+1024-off] : 0);
        dst[t] = a0; dst[t+1024] = a1;
        int* tmp = src; src = dst; dst = tmp;
    }
    __syncthreads();
    if (i0 < len) g_rowptr[i0] = src[t]      - v0;
    if (i1 < len) g_rowptr[i1] = src[t+1024] - v1;
    if (t == 0) g_bsum[blockIdx.x] = src[2047];
}

__global__ void k_scanB(int nb) {
    if (threadIdx.x == 0) {
        int run = 0;
        for (int i = 0; i < nb; i++) { int v = g_bsum[i]; g_bsum[i] = run; run += v; }
    }
}

// finalize rowptr; also seed g_cur and compute dis = rsqrt(deg+1)
__global__ void k_scanC(int len, int NL) {
    int base = blockIdx.x*2048;
    int add = g_bsum[blockIdx.x];
    int i0 = base + threadIdx.x, i1 = i0 + 1024;
    if (i0 < len) {
        int v = g_rowptr[i0] + add; g_rowptr[i0] = v;
        if (i0 < NL) { g_cur[i0] = v; g_dis[i0] = rsqrtf((float)(g_cnt[i0] + 1)); }
    }
    if (i1 < len) {
        int v = g_rowptr[i1] + add; g_rowptr[i1] = v;
        if (i1 < NL) { g_cur[i1] = v; g_dis[i1] = rsqrtf((float)(g_cnt[i1] + 1)); }
    }
}

__global__ void k_fill() {
    int e = blockIdx.x*blockDim.x + threadIdx.x;
    if (e >= ET) return;
    int s = g_esrc[e];
    if (s < 0) return;
    int d = g_edst[e];
    int p = atomicAdd(&g_cur[d], 1);
    g_col[p] = s;
}

// per-row insertion sort -> bitwise-deterministic summation order
__global__ void k_sortrows(int NL) {
    int node = blockIdx.x*blockDim.x + threadIdx.x;
    if (node >= NL) return;
    int beg = g_rowptr[node], end = g_rowptr[node+1];
    for (int i = beg + 1; i < end; i++) {
        int v = g_col[i]; int j = i - 1;
        while (j >= beg && g_col[j] > v) { g_col[j+1] = g_col[j]; j--; }
        g_col[j+1] = v;
    }
}

// ---------------- SGEMM: g_H[M x 128] = A[M x K] * W[K x 128] ----------------
// 128x128 tile, 256 threads, 8x8 per-thread tile accumulated in packed f32x2
// pairs (FFMA2 = 2x fp32 throughput on sm_103a), double-buffered smem.
template<int K>
__global__ __launch_bounds__(256) void k_sgemm(const float* __restrict__ Aext,
                                               const float* __restrict__ W, int M) {
    const float* __restrict__ A = Aext ? Aext : g_bufB;
    __shared__ float As[2][16][128];   // transposed A tile: As[k][row]
    __shared__ float Bs[2][16][128];
    int tid = threadIdx.x;
    int ty = tid >> 4, tx = tid & 15;
    int rowBase = blockIdx.x * 128;

    unsigned long long acc[8][4];
    #pragma unroll
    for (int i = 0; i < 8; i++)
        #pragma unroll
        for (int j = 0; j < 4; j++) acc[i][j] = 0ull;

    // stage tile 0 directly to smem
    #pragma unroll
    for (int l = 0; l < 2; l++) {
        int f = tid + l*256;
        int r = f >> 2, c = (f & 3) << 2;
        int gr = rowBase + r;
        float4 v = make_float4(0.f,0.f,0.f,0.f);
        if (gr < M) v = *(const float4*)(A + (size_t)gr*K + c);
        As[0][c+0][r] = v.x; As[0][c+1][r] = v.y; As[0][c+2][r] = v.z; As[0][c+3][r] = v.w;
    }
    #pragma unroll
    for (int l = 0; l < 2; l++) {
        int f = tid + l*256;
        int r = f >> 5, c = (f & 31) << 2;
        *(float4*)&Bs[0][r][c] = *(const float4*)(W + (size_t)r*128 + c);
    }
    __syncthreads();

    const int T = K / 16;
    for (int t = 0; t < T; t++) {
        int cur = t & 1, nxt = cur ^ 1;
        float4 pva[2], pvb[2];
        if (t + 1 < T) {
            int k0 = (t + 1) * 16;
            #pragma unroll
            for (int l = 0; l < 2; l++) {
                int f = tid + l*256;
                int r = f >> 2, c = (f & 3) << 2;
                int gr = rowBase + r;
                pva[l] = make_float4(0.f,0.f,0.f,0.f);
                if (gr < M) pva[l] = *(const float4*)(A + (size_t)gr*K + k0 + c);
            }
            #pragma unroll
            for (int l = 0; l < 2; l++) {
                int f = tid + l*256;
                int r = f >> 5, c = (f & 31) << 2;
                pvb[l] = *(const float4*)(W + (size_t)(k0+r)*128 + c);
            }
        }
        #pragma unroll
        for (int kk = 0; kk < 16; kk++) {
            float a[8];
            *(float4*)&a[0] = *(float4*)&As[cur][kk][ty*8];
            *(float4*)&a[4] = *(float4*)&As[cur][kk][ty*8+4];
            float4 b0 = *(float4*)&Bs[cur][kk][tx*8];
            float4 b1 = *(float4*)&Bs[cur][kk][tx*8+4];
            unsigned long long bp0 = pk2(b0.x, b0.y);
            unsigned long long bp1 = pk2(b0.z, b0.w);
            unsigned long long bp2 = pk2(b1.x, b1.y);
            unsigned long long bp3 = pk2(b1.z, b1.w);
            #pragma unroll
            for (int i = 0; i < 8; i++) {
                unsigned long long ad = pk2(a[i], a[i]);
                fma2(acc[i][0], ad, bp0);
                fma2(acc[i][1], ad, bp1);
                fma2(acc[i][2], ad, bp2);
                fma2(acc[i][3], ad, bp3);
            }
        }
        if (t + 1 < T) {
            #pragma unroll
            for (int l = 0; l < 2; l++) {
                int f = tid + l*256;
                int r = f >> 2, c = (f & 3) << 2;
                As[nxt][c+0][r] = pva[l].x; As[nxt][c+1][r] = pva[l].y;
                As[nxt][c+2][r] = pva[l].z; As[nxt][c+3][r] = pva[l].w;
            }
            #pragma unroll
            for (int l = 0; l < 2; l++) {
                int f = tid + l*256;
                int r = f >> 5, c = (f & 31) << 2;
                *(float4*)&Bs[nxt][r][c] = pvb[l];
            }
            __syncthreads();
        }
    }

    #pragma unroll
    for (int i = 0; i < 8; i++) {
        int gr = rowBase + ty*8 + i;
        if (gr < M) {
            float o[8];
            upk2(acc[i][0], o[0], o[1]); upk2(acc[i][1], o[2], o[3]);
            upk2(acc[i][2], o[4], o[5]); upk2(acc[i][3], o[6], o[7]);
            *(float4*)(g_H + (size_t)gr*128 + tx*8)     = *(float4*)&o[0];
            *(float4*)(g_H + (size_t)gr*128 + tx*8 + 4) = *(float4*)&o[4];
        }
    }
}

// ---------------- GCN aggregation (warp per node, float4 per lane) ----------------
// Also fuses the score-GEMV (sh = out . Ws) while the output row is in registers.
__global__ void k_agg_main(const float* __restrict__ bias, const float* __restrict__ Ws,
                           int NL) {
    int node = (blockIdx.x*blockDim.x + threadIdx.x) >> 5;
    int lane = threadIdx.x & 31;
    if (node >= NL) return;
    const float4* H4 = (const float4*)g_H;
    float4 acc = make_float4(0.f,0.f,0.f,0.f);
    int beg = g_rowptr[node], end = g_rowptr[node+1];
    for (int eb = beg; eb < end; eb += 32) {
        int m = min(32, end - eb);
        int   sl = (lane < m) ? g_col[eb + lane] : 0;
        float dl = (lane < m) ? g_dis[sl] : 0.f;
        for (int q = 0; q < m; q++) {
            int   s  = __shfl_sync(0xffffffffu, sl, q);
            float ds = __shfl_sync(0xffffffffu, dl, q);
            float4 h = H4[(size_t)s*32 + lane];
            acc.x = fmaf(h.x, ds, acc.x);
            acc.y = fmaf(h.y, ds, acc.y);
            acc.z = fmaf(h.z, ds, acc.z);
            acc.w = fmaf(h.w, ds, acc.w);
        }
    }
    float dd  = g_dis[node];
    float inv = 1.0f / (float)(g_cnt[node] + 1);
    float4 hs = H4[(size_t)node*32 + lane];
    float4 b4 = ((const float4*)bias)[lane];
    float4 o;
    o.x = fmaxf(acc.x*dd + hs.x*inv + b4.x, 0.f);
    o.y = fmaxf(acc.y*dd + hs.y*inv + b4.y, 0.f);
    o.z = fmaxf(acc.z*dd + hs.z*inv + b4.z, 0.f);
    o.w = fmaxf(acc.w*dd + hs.w*inv + b4.w, 0.f);
    ((float4*)g_bufA)[(size_t)node*32 + lane] = o;

    // fused score GEMV: sh[node] = out_row . Ws
    float4 w4 = ((const float4*)Ws)[lane];
    float s = o.x*w4.x + o.y*w4.y + o.z*w4.z + o.w*w4.w;
    #pragma unroll
    for (int off = 16; off; off >>= 1) s += __shfl_xor_sync(0xffffffffu, s, off);
    if (lane == 0) g_sh[node] = s;
}

// reset map for topk (cnt zeroing happens later, in k_gather — AFTER k_topk
// has consumed this layer's degrees)
__global__ void k_fillmap(int NL) {
    int i = blockIdx.x*blockDim.x + threadIdx.x;
    if (i < NL) g_map[i] = -1;
}

// Per-graph: compute SAGPool scores (edges never cross graphs) then top-k via
// bitonic sort of 2048 packed (score desc, idx asc) keys.
__global__ void k_topk(const float* __restrict__ bs, int n, int k) {
    __shared__ unsigned long long key[2048];
    __shared__ float sc[2048];
    int b = blockIdx.x;
    float bsv = bs[0];
    for (int j = threadIdx.x; j < 2048; j += 1024) {
        unsigned long long kk;
        if (j < n) {
            int node = b*n + j;
            float acc = 0.f;
            int beg = g_rowptr[node], end = g_rowptr[node+1];
            for (int e = beg; e < end; e++) {
                int s = g_col[e];
                acc = fmaf(g_sh[s], g_dis[s], acc);
            }
            float inv = 1.0f / (float)(g_cnt[node] + 1);
            float scv = acc*g_dis[node] + g_sh[node]*inv + bsv;
            sc[j] = scv;
            unsigned int u = __float_as_uint(scv);
            u = (u & 0x80000000u) ? ~u : (u | 0x80000000u);  // monotone float->uint
            kk = ((unsigned long long)(~u) << 32) | (unsigned int)j;  // asc = score desc
        } else kk = 0xFFFFFFFFFFFFFFFFull;
        key[j] = kk;
    }
    for (int sz = 2; sz <= 2048; sz <<= 1)
        for (int st = sz >> 1; st > 0; st >>= 1) {
            __syncthreads();
            #pragma unroll 1
            for (int t = threadIdx.x; t < 2048; t += 1024) {
                int ixj = t ^ st;
                if (ixj > t) {
                    unsigned long long a = key[t], c = key[ixj];
                    bool up = ((t & sz) == 0);
                    if ((a > c) == up) { key[t] = c; key[ixj] = a; }
                }
            }
        }
    __syncthreads();
    for (int j = threadIdx.x; j < k; j += 1024) {
        int idx  = (int)(unsigned int)(key[j] & 0xffffffffull);
        int oldg = b*n + idx;
        int newg = b*k + j;
        g_perm[newg] = oldg;
        g_gmul[newg] = tanhf(sc[idx]);
        g_map[oldg]  = newg;
    }
}

// gather pooled features; also zero g_cnt for the NEXT layer (safe window:
// after k_topk read this layer's cnt, before k_remap counts the next)
__global__ void k_gather(int newN) {
    int i = blockIdx.x*blockDim.x + threadIdx.x;
    int node = i >> 5, lane = i & 31;
    if (node >= newN) return;
    int s = g_perm[node];
    float g = g_gmul[node];
    float4 v = ((const float4*)g_bufA)[(size_t)s*32 + lane];
    v.x *= g; v.y *= g; v.z *= g; v.w *= g;
    ((float4*)g_bufB)[(size_t)node*32 + lane] = v;
    if (lane == 0) g_cnt[node] = 0;
}

// relabel surviving edges + count in-degrees for the next layer
__global__ void k_remap() {
    int e = blockIdx.x*blockDim.x + threadIdx.x;
    if (e >= ET) return;
    int s = g_esrc[e];
    if (s < 0) return;
    int ns = g_map[s], nd = g_map[g_edst[e]];
    if (ns >= 0 && nd >= 0) {
        g_esrc[e] = ns; g_edst[e] = nd;
        atomicAdd(&g_cnt[nd], 1);
    } else g_esrc[e] = -1;
}

// readout: max || mean over each graph's k nodes (x is pooled = g_bufB)
__global__ void k_readout(int kcnt, int layer) {
    int b = blockIdx.x;
    int g = threadIdx.x >> 7;      // 8 groups
    int f = threadIdx.x & 127;
    float m = -INFINITY, s = 0.f;
    for (int j = g; j < kcnt; j += 8) {
        float v = g_bufB[(size_t)(b*kcnt + j)*NH + f];
        m = fmaxf(m, v); s += v;
    }
    __shared__ float sm[8][128], ss[8][128];
    sm[g][f] = m; ss[g][f] = s;
    __syncthreads();
    if (g == 0) {
        #pragma unroll
        for (int q = 1; q < 8; q++) { m = fmaxf(m, sm[q][f]); s += ss[q][f]; }
        float* R = g_R + (size_t)layer*NB*256 + (size_t)b*256;
        R[f]       = m;
        R[128 + f] = s / (float)kcnt;
    }
}

__global__ void k_final(const float* __restrict__ Wl, const float* __restrict__ bl,
                        float* __restrict__ out) {
    int b = blockIdx.x;
    int f = threadIdx.x;   // 128
    __shared__ float s[256];
    for (int c = f; c < 256; c += 128)
        s[c] = g_R[b*256 + c] + g_R[NB*256 + b*256 + c] + g_R[2*NB*256 + b*256 + c];
    __syncthreads();
    float acc = bl[f];
    #pragma unroll 8
    for (int c = 0; c < 256; c++) acc = fmaf(s[c], Wl[c*128 + f], acc);
    out[b*128 + f] = fmaxf(acc, 0.f);
}

// ---------------- driver ----------------
extern "C" void kernel_launch(void* const* d_in, const int* in_sizes, int n_in,
                              void* d_out, int out_size) {
    const float* x   = (const float*)d_in[0];
    const float* W_[3]  = { (const float*)d_in[1], (const float*)d_in[5], (const float*)d_in[9]  };
    const float* b_[3]  = { (const float*)d_in[2], (const float*)d_in[6], (const float*)d_in[10] };
    const float* Ws_[3] = { (const float*)d_in[3], (const float*)d_in[7], (const float*)d_in[11] };
    const float* bs_[3] = { (const float*)d_in[4], (const float*)d_in[8], (const float*)d_in[12] };
    const float* Wl = (const float*)d_in[13];
    const float* bl = (const float*)d_in[14];
    const int*   ei = (const int*)d_in[15];
    float* out = (float*)d_out;

    const int EB = (ET + 255) / 256;

    // layer-0 edge init + degree count
    k_zero_cnt  <<<(N0 + 255) / 256, 256>>>(N0);
    k_init_edges<<<EB, 256>>>(ei);

    int n  = NPG;
    int NL = N0;
    for (int L = 0; L < 3; L++) {
        int kk  = (n * 4) / 5;              // ceil(0.8*n) exact for 2000/1600/1280
        int len = NL + 1;
        int nb  = (len + 2047) / 2048;
        int NLB = (NL + 255) / 256;

        // ---- CSR build (dst-major), deterministic ----
        k_scanA   <<<nb, 1024>>>(len, NL);
        k_scanB   <<<1, 32>>>(nb);
        k_scanC   <<<nb, 1024>>>(len, NL);   // + g_cur + g_dis
        k_fill    <<<EB, 256>>>();
        k_sortrows<<<NLB, 256>>>(NL);

        // ---- GCN conv (H = Xin @ W; agg + self + bias + relu -> bufA; + score GEMV) ----
        if (L == 0) k_sgemm<FIN><<<(NL + 127) / 128, 256>>>(x,       W_[L], NL);
        else        k_sgemm<NH> <<<(NL + 127) / 128, 256>>>(nullptr, W_[L], NL);
        k_agg_main<<<(NL + 7) / 8, 256>>>(b_[L], Ws_[L], NL);

        // ---- SAG pool (scores computed inside k_topk, per-graph) ----
        if (L < 2) k_fillmap<<<NLB, 256>>>(NL);   // map=-1 only (cnt still live!)
        k_topk <<<NB, 1024>>>(bs_[L], n, kk);
        int newN = NB * kk;
        k_gather<<<(newN*32 + 255) / 256, 256>>>(newN);   // + zero cnt for next layer
        if (L < 2) k_remap<<<EB, 256>>>();        // relabel + count next layer

        // ---- readout on pooled x ----
        k_readout<<<NB, 1024>>>(kk, L);

        n = kk; NL = newN;
    }
    k_final<<<NB, 128>>>(Wl, bl, out);
    (void)in_sizes; (void)n_in; (void)out_size;
}